// round 7
// baseline (speedup 1.0000x reference)
#include <cuda_runtime.h>

// ---------------- geometry ----------------
#define RB0 677
#define RB1 338
#define RB2 169
#define RB_TOT (RB0 + RB1 + RB2)   // 1184

// ---------------- scratch ----------------
__device__ double g_part_sq[RB_TOT];
__device__ double g_part_m[48];        // 16 img x 3 levels
__device__ int    g_counter = 0;       // reset by last block each call
__device__ float  g_mask0[16 * 80 * 80];
__device__ float  g_mask1[16 * 40 * 40];
__device__ float  g_mask2[16 * 20 * 20];

// ---------------- block reduce (valid in thread 0) ----------------
__device__ __forceinline__ float block_reduce(float v) {
    #pragma unroll
    for (int o = 16; o > 0; o >>= 1) v += __shfl_down_sync(0xffffffffu, v, o);
    __shared__ float ws[8];
    const int lane = threadIdx.x & 31, wid = threadIdx.x >> 5;
    if (lane == 0) ws[wid] = v;
    __syncthreads();
    if (wid == 0) {
        v = (lane < 8) ? ws[lane] : 0.0f;
        #pragma unroll
        for (int o = 4; o > 0; o >>= 1) v += __shfl_down_sync(0xffffffffu, v, o);
    }
    return v;
}

// ---------------- mask kernel: 48 blocks (16 img x 3 levels) ----------------
template <int S>
__device__ __forceinline__ void mask_plane(
    const float* __restrict__ bboxes, const int* __restrict__ bidx, int nbox,
    float* __restrict__ mout, int b)
{
    __shared__ int   cnt;
    __shared__ float s_xc[64], s_yc[64], s_iw[64], s_ih[64];
    __shared__ int   s_xl[64], s_xr[64], s_yt[64], s_yd[64];
    if (threadIdx.x == 0) cnt = 0;
    __syncthreads();
    for (int i = threadIdx.x; i < nbox; i += blockDim.x) {
        if (bidx[i] == b) {
            int xc = (int)floorf(bboxes[4 * i + 0] * (float)S);
            int yc = (int)floorf(bboxes[4 * i + 1] * (float)S);
            int w  = (int)floorf(bboxes[4 * i + 2] * (float)S);
            int h  = (int)floorf(bboxes[4 * i + 3] * (float)S);
            int xl = max(xc - w / 2, 0), xr = min(xc + w / 2, S - 1);
            int yt = max(yc - h / 2, 0), yd = min(yc + h / 2, S - 1);
            float wd = (float)(xr - xl + 1), ht = (float)(yd - yt + 1);
            int q = atomicAdd(&cnt, 1);
            s_xc[q] = (float)xc; s_yc[q] = (float)yc;
            // STD^2*(w/2)^2 == w^2 for STD=2
            s_iw[q] = 1.0f / (wd * wd); s_ih[q] = 1.0f / (ht * ht);
            s_xl[q] = xl; s_xr[q] = xr; s_yt[q] = yt; s_yd[q] = yd;
        }
    }
    __syncthreads();
    const int n = cnt;

    float msum = 0.0f;
    for (int pix = threadIdx.x; pix < S * S; pix += 256) {
        const int y = pix / S, x = pix % S;
        const float fx = (float)x, fy = (float)y;
        float m = 0.0f;
        for (int i = 0; i < n; i++) {
            if (x >= s_xl[i] && x <= s_xr[i] && y >= s_yt[i] && y <= s_yd[i]) {
                float dx = fx - s_xc[i], dy = fy - s_yc[i];
                float v = __expf(-(dx * dx * s_iw[i] + dy * dy * s_ih[i]));
                m = fmaxf(m, v);
            }
        }
        mout[b * S * S + pix] = m;
        msum += m;
    }
    float v = block_reduce(msum);
    if (threadIdx.x == 0) g_part_m[blockIdx.x] = (double)v;
}

__global__ void __launch_bounds__(256) mask_kernel(
    const float* __restrict__ bboxes, const int* __restrict__ bidx, int nbox)
{
    const int blk = blockIdx.x;
    if      (blk < 16) mask_plane<80>(bboxes, bidx, nbox, g_mask0, blk);
    else if (blk < 32) mask_plane<40>(bboxes, bidx, nbox, g_mask1, blk - 16);
    else               mask_plane<20>(bboxes, bidx, nbox, g_mask2, blk - 32);
}

// ---------------- reduce worker: linear stream, batch-of-4 MLP ----------------
template <int C, int S>
__device__ __forceinline__ float reduce_stream(
    const float4* __restrict__ pp, const float4* __restrict__ tt,
    const float4* __restrict__ mm, int blk, int nblk)
{
    constexpr int HW4 = S * S / 4;
    constexpr int CHW4 = C * HW4;     // float4s per image
    constexpr int N4  = 16 * CHW4;
    const int step = nblk * 1024;

    float a0 = 0.f, a1 = 0.f, a2 = 0.f, a3 = 0.f;
    int i = blk * 1024 + threadIdx.x;

    while (i + 768 < N4) {
        const int i0 = i, i1 = i + 256, i2 = i + 512, i3 = i + 768;
        // per-image mask slot: b*HW4 + (i % HW4)
        const int m0i = (i0 / CHW4) * HW4 + (i0 % HW4);
        const int m1i = (i1 / CHW4) * HW4 + (i1 % HW4);
        const int m2i = (i2 / CHW4) * HW4 + (i2 % HW4);
        const int m3i = (i3 / CHW4) * HW4 + (i3 % HW4);
        // front-batched loads (12 in flight)
        float4 pv0 = pp[i0], pv1 = pp[i1], pv2 = pp[i2], pv3 = pp[i3];
        float4 tv0 = tt[i0], tv1 = tt[i1], tv2 = tt[i2], tv3 = tt[i3];
        float4 mv0 = mm[m0i], mv1 = mm[m1i], mv2 = mm[m2i], mv3 = mm[m3i];
        float d;
        d = pv0.x - tv0.x; a0 += d * d * mv0.x * mv0.x;
        d = pv0.y - tv0.y; a0 += d * d * mv0.y * mv0.y;
        d = pv0.z - tv0.z; a0 += d * d * mv0.z * mv0.z;
        d = pv0.w - tv0.w; a0 += d * d * mv0.w * mv0.w;
        d = pv1.x - tv1.x; a1 += d * d * mv1.x * mv1.x;
        d = pv1.y - tv1.y; a1 += d * d * mv1.y * mv1.y;
        d = pv1.z - tv1.z; a1 += d * d * mv1.z * mv1.z;
        d = pv1.w - tv1.w; a1 += d * d * mv1.w * mv1.w;
        d = pv2.x - tv2.x; a2 += d * d * mv2.x * mv2.x;
        d = pv2.y - tv2.y; a2 += d * d * mv2.y * mv2.y;
        d = pv2.z - tv2.z; a2 += d * d * mv2.z * mv2.z;
        d = pv2.w - tv2.w; a2 += d * d * mv2.w * mv2.w;
        d = pv3.x - tv3.x; a3 += d * d * mv3.x * mv3.x;
        d = pv3.y - tv3.y; a3 += d * d * mv3.y * mv3.y;
        d = pv3.z - tv3.z; a3 += d * d * mv3.z * mv3.z;
        d = pv3.w - tv3.w; a3 += d * d * mv3.w * mv3.w;
        i += step;
    }
    // tail
    #pragma unroll
    for (int u = 0; u < 4; u++) {
        const int ii = i + u * 256;
        if (ii < N4) {
            float4 pv = pp[ii], tv = tt[ii];
            float4 mv = mm[(ii / CHW4) * HW4 + (ii % HW4)];
            float d;
            d = pv.x - tv.x; a0 += d * d * mv.x * mv.x;
            d = pv.y - tv.y; a0 += d * d * mv.y * mv.y;
            d = pv.z - tv.z; a0 += d * d * mv.z * mv.z;
            d = pv.w - tv.w; a0 += d * d * mv.w * mv.w;
        }
    }
    return (a0 + a1) + (a2 + a3);
}

// ---------------- reduce kernel (+ fused finalize in last block) ----------------
__global__ void __launch_bounds__(256) reduce_kernel(
    const float4* __restrict__ p0, const float4* __restrict__ t0,
    const float4* __restrict__ p1, const float4* __restrict__ t1,
    const float4* __restrict__ p2, const float4* __restrict__ t2,
    float* __restrict__ out)
{
    const int blk = blockIdx.x;
    float acc;
    if (blk < RB0)
        acc = reduce_stream<128, 80>(p0, t0, (const float4*)g_mask0, blk, RB0);
    else if (blk < RB0 + RB1)
        acc = reduce_stream<256, 40>(p1, t1, (const float4*)g_mask1, blk - RB0, RB1);
    else
        acc = reduce_stream<512, 20>(p2, t2, (const float4*)g_mask2, blk - (RB0 + RB1), RB2);

    float v = block_reduce(acc);
    if (threadIdx.x == 0) g_part_sq[blockIdx.x] = (double)v;

    // ---- last block finalizes ----
    __shared__ bool is_last;
    __threadfence();
    if (threadIdx.x == 0) {
        int prev = atomicAdd(&g_counter, 1);
        is_last = (prev == RB_TOT - 1);
    }
    __syncthreads();
    if (!is_last) return;

    __shared__ double sd[256];
    double q[3], m[3];
    const int qlo[4] = {0, RB0, RB0 + RB1, RB_TOT};
    for (int l = 0; l < 3; l++) {
        double s = 0.0;
        for (int i = qlo[l] + threadIdx.x; i < qlo[l + 1]; i += 256) s += g_part_sq[i];
        sd[threadIdx.x] = s;
        __syncthreads();
        for (int o = 128; o > 0; o >>= 1) {
            if (threadIdx.x < o) sd[threadIdx.x] += sd[threadIdx.x + o];
            __syncthreads();
        }
        q[l] = sd[0];
        __syncthreads();
        // m partials: 16 entries per level
        double sm = (threadIdx.x < 16) ? g_part_m[l * 16 + threadIdx.x] : 0.0;
        sd[threadIdx.x] = sm;
        __syncthreads();
        for (int o = 8; o > 0; o >>= 1) {
            if (threadIdx.x < o) sd[threadIdx.x] += sd[threadIdx.x + o];
            __syncthreads();
        }
        m[l] = sd[0];
        __syncthreads();
    }
    if (threadIdx.x == 0) {
        double total = q[0] / (128.0 * m[0]) + q[1] / (256.0 * m[1]) + q[2] / (512.0 * m[2]);
        out[0] = (float)(total / 3.0);
        g_counter = 0;
    }
}

extern "C" void kernel_launch(void* const* d_in, const int* in_sizes, int n_in,
                              void* d_out, int out_size)
{
    // metadata order is INTERLEAVED: pred0, true0, pred1, true1, pred2, true2
    const float* p0 = (const float*)d_in[0];
    const float* t0 = (const float*)d_in[1];
    const float* p1 = (const float*)d_in[2];
    const float* t1 = (const float*)d_in[3];
    const float* p2 = (const float*)d_in[4];
    const float* t2 = (const float*)d_in[5];
    const float* bboxes = (const float*)d_in[6];
    const int* bidx = (const int*)d_in[8];
    const int nbox = in_sizes[8];
    float* out = (float*)d_out;

    mask_kernel<<<48, 256>>>(bboxes, bidx, nbox);
    reduce_kernel<<<RB_TOT, 256>>>(
        (const float4*)p0, (const float4*)t0,
        (const float4*)p1, (const float4*)t1,
        (const float4*)p2, (const float4*)t2, out);
}

// round 11
// speedup vs baseline: 2.2009x; 2.2009x over previous
#include <cuda_runtime.h>

#define GRID_R 444          // 148 SMs x 3 blocks
#define NLEV 3

// ---------------- scratch ----------------
__device__ double g_part_sq[NLEV][GRID_R];
__device__ double g_part_m [NLEV][GRID_R];
__device__ int    g_counter = 0;
__device__ float  g_mask0[16 * 80 * 80];
__device__ float  g_mask1[16 * 40 * 40];
__device__ float  g_mask2[16 * 20 * 20];

// ---------------- block reduce (valid in thread 0) ----------------
__device__ __forceinline__ float block_reduce(float v) {
    #pragma unroll
    for (int o = 16; o > 0; o >>= 1) v += __shfl_down_sync(0xffffffffu, v, o);
    __shared__ float ws[8];
    const int lane = threadIdx.x & 31, wid = threadIdx.x >> 5;
    if (lane == 0) ws[wid] = v;
    __syncthreads();
    if (wid == 0) {
        v = (lane < 8) ? ws[lane] : 0.0f;
        #pragma unroll
        for (int o = 4; o > 0; o >>= 1) v += __shfl_down_sync(0xffffffffu, v, o);
    }
    return v;
}

// ---------------- 1) zero masks ----------------
__global__ void __launch_bounds__(256) zero_kernel() {
    const int i = blockIdx.x * 256 + threadIdx.x;
    const float4 z = make_float4(0.f, 0.f, 0.f, 0.f);
    if (i < 25600) ((float4*)g_mask0)[i] = z;
    if (i < 6400)  ((float4*)g_mask1)[i] = z;
    if (i < 1600)  ((float4*)g_mask2)[i] = z;
}

// ---------------- 2) box-parallel scatter ----------------
template <int S>
__device__ __forceinline__ void scatter_box(
    const float* __restrict__ bboxes, const int* __restrict__ bidx,
    int k, float* __restrict__ mask)
{
    const int b = bidx[k];
    const float4 bb = ((const float4*)bboxes)[k];
    const int xc = (int)floorf(bb.x * (float)S);
    const int yc = (int)floorf(bb.y * (float)S);
    const int w  = (int)floorf(bb.z * (float)S);
    const int h  = (int)floorf(bb.w * (float)S);
    const int xl = max(xc - w / 2, 0), xr = min(xc + w / 2, S - 1);
    const int yt = max(yc - h / 2, 0), yd = min(yc + h / 2, S - 1);
    const float wd = (float)(xr - xl + 1), ht = (float)(yd - yt + 1);
    // STD^2*(w/2)^2 == w^2 for STD=2
    const float iw = 1.0f / (wd * wd), ih = 1.0f / (ht * ht);
    const int bw = xr - xl + 1;
    const int cnt = bw * (yd - yt + 1);
    int* mp = (int*)(mask + (size_t)b * S * S);

    for (int idx = threadIdx.x; idx < cnt; idx += 256) {
        const int px = xl + idx % bw;
        const int py = yt + idx / bw;
        const float dx = (float)px - (float)xc, dy = (float)py - (float)yc;
        const float v = __expf(-(dx * dx * iw + dy * dy * ih));
        atomicMax(mp + py * S + px, __float_as_int(v));   // values >= 0: int-max == float-max
    }
}

__global__ void __launch_bounds__(256) scatter_kernel(
    const float* __restrict__ bboxes, const int* __restrict__ bidx, int nbox)
{
    const int lev = blockIdx.x / nbox;
    const int k   = blockIdx.x - lev * nbox;
    if      (lev == 0) scatter_box<80>(bboxes, bidx, k, g_mask0);
    else if (lev == 1) scatter_box<40>(bboxes, bidx, k, g_mask1);
    else               scatter_box<20>(bboxes, bidx, k, g_mask2);
}

// ---------------- 3) streaming reduce (all blocks, one level at a time) ----------------
template <int C, int S>
__device__ __forceinline__ void stream_level(
    const float4* __restrict__ pp, const float4* __restrict__ tt,
    const float4* __restrict__ mm, int lev)
{
    constexpr int HW4  = S * S / 4;
    constexpr int CHW4 = C * HW4;
    constexpr int N4   = 16 * CHW4;
    const int step = GRID_R * 1024;

    float q0 = 0.f, q1 = 0.f, q2 = 0.f, q3 = 0.f, ms = 0.f;
    int i = blockIdx.x * 1024 + threadIdx.x;

    for (; i + 768 < N4; i += step) {
        const int i0 = i, i1 = i + 256, i2 = i + 512, i3 = i + 768;
        const int b0 = i0 / CHW4, b1 = i1 / CHW4, b2 = i2 / CHW4, b3 = i3 / CHW4;
        const int r0 = i0 - b0 * CHW4, r1 = i1 - b1 * CHW4;
        const int r2 = i2 - b2 * CHW4, r3 = i3 - b3 * CHW4;
        const int x0 = i0 % HW4, x1 = i1 % HW4, x2 = i2 % HW4, x3 = i3 % HW4;
        // front-batched loads (12 in flight)
        const float4 pv0 = pp[i0], pv1 = pp[i1], pv2 = pp[i2], pv3 = pp[i3];
        const float4 tv0 = tt[i0], tv1 = tt[i1], tv2 = tt[i2], tv3 = tt[i3];
        const float4 mv0 = mm[b0 * HW4 + x0], mv1 = mm[b1 * HW4 + x1];
        const float4 mv2 = mm[b2 * HW4 + x2], mv3 = mm[b3 * HW4 + x3];
        float d;
        d = pv0.x - tv0.x; q0 += d * d * mv0.x * mv0.x;
        d = pv0.y - tv0.y; q0 += d * d * mv0.y * mv0.y;
        d = pv0.z - tv0.z; q0 += d * d * mv0.z * mv0.z;
        d = pv0.w - tv0.w; q0 += d * d * mv0.w * mv0.w;
        d = pv1.x - tv1.x; q1 += d * d * mv1.x * mv1.x;
        d = pv1.y - tv1.y; q1 += d * d * mv1.y * mv1.y;
        d = pv1.z - tv1.z; q1 += d * d * mv1.z * mv1.z;
        d = pv1.w - tv1.w; q1 += d * d * mv1.w * mv1.w;
        d = pv2.x - tv2.x; q2 += d * d * mv2.x * mv2.x;
        d = pv2.y - tv2.y; q2 += d * d * mv2.y * mv2.y;
        d = pv2.z - tv2.z; q2 += d * d * mv2.z * mv2.z;
        d = pv2.w - tv2.w; q2 += d * d * mv2.w * mv2.w;
        d = pv3.x - tv3.x; q3 += d * d * mv3.x * mv3.x;
        d = pv3.y - tv3.y; q3 += d * d * mv3.y * mv3.y;
        d = pv3.z - tv3.z; q3 += d * d * mv3.z * mv3.z;
        d = pv3.w - tv3.w; q3 += d * d * mv3.w * mv3.w;
        // sum(m): count each mask element once (channel 0 of its image)
        if (r0 < HW4) ms += (mv0.x + mv0.y) + (mv0.z + mv0.w);
        if (r1 < HW4) ms += (mv1.x + mv1.y) + (mv1.z + mv1.w);
        if (r2 < HW4) ms += (mv2.x + mv2.y) + (mv2.z + mv2.w);
        if (r3 < HW4) ms += (mv3.x + mv3.y) + (mv3.z + mv3.w);
    }
    // tail
    #pragma unroll
    for (int u = 0; u < 3; u++) {
        const int ii = i + u * 256;
        if (ii < N4) {
            const int b = ii / CHW4, r = ii - b * CHW4, x = ii % HW4;
            const float4 pv = pp[ii], tv = tt[ii], mv = mm[b * HW4 + x];
            float d;
            d = pv.x - tv.x; q0 += d * d * mv.x * mv.x;
            d = pv.y - tv.y; q0 += d * d * mv.y * mv.y;
            d = pv.z - tv.z; q0 += d * d * mv.z * mv.z;
            d = pv.w - tv.w; q0 += d * d * mv.w * mv.w;
            if (r < HW4) ms += (mv.x + mv.y) + (mv.z + mv.w);
        }
    }

    float qb = block_reduce((q0 + q1) + (q2 + q3));
    __syncthreads();
    float mb = block_reduce(ms);
    if (threadIdx.x == 0) {
        g_part_sq[lev][blockIdx.x] = (double)qb;
        g_part_m [lev][blockIdx.x] = (double)mb;
    }
    __syncthreads();
}

__global__ void __launch_bounds__(256, 3) reduce_kernel(
    const float4* __restrict__ p0, const float4* __restrict__ t0,
    const float4* __restrict__ p1, const float4* __restrict__ t1,
    const float4* __restrict__ p2, const float4* __restrict__ t2,
    float* __restrict__ out)
{
    stream_level<128, 80>(p0, t0, (const float4*)g_mask0, 0);
    stream_level<256, 40>(p1, t1, (const float4*)g_mask1, 1);
    stream_level<512, 20>(p2, t2, (const float4*)g_mask2, 2);

    // ---- last block finalizes ----
    __shared__ bool is_last;
    __threadfence();
    if (threadIdx.x == 0) {
        int prev = atomicAdd(&g_counter, 1);
        is_last = (prev == GRID_R - 1);
    }
    __syncthreads();
    if (!is_last) return;

    __shared__ double sd[256];
    double q[3], m[3];
    for (int l = 0; l < 3; l++) {
        double s = 0.0;
        for (int i = threadIdx.x; i < GRID_R; i += 256) s += g_part_sq[l][i];
        sd[threadIdx.x] = s;
        __syncthreads();
        for (int o = 128; o > 0; o >>= 1) {
            if (threadIdx.x < o) sd[threadIdx.x] += sd[threadIdx.x + o];
            __syncthreads();
        }
        q[l] = sd[0];
        __syncthreads();
        s = 0.0;
        for (int i = threadIdx.x; i < GRID_R; i += 256) s += g_part_m[l][i];
        sd[threadIdx.x] = s;
        __syncthreads();
        for (int o = 128; o > 0; o >>= 1) {
            if (threadIdx.x < o) sd[threadIdx.x] += sd[threadIdx.x + o];
            __syncthreads();
        }
        m[l] = sd[0];
        __syncthreads();
    }
    if (threadIdx.x == 0) {
        double total = q[0] / (128.0 * m[0]) + q[1] / (256.0 * m[1]) + q[2] / (512.0 * m[2]);
        out[0] = (float)(total / 3.0);
        g_counter = 0;
    }
}

extern "C" void kernel_launch(void* const* d_in, const int* in_sizes, int n_in,
                              void* d_out, int out_size)
{
    // metadata order is INTERLEAVED: pred0, true0, pred1, true1, pred2, true2
    const float* p0 = (const float*)d_in[0];
    const float* t0 = (const float*)d_in[1];
    const float* p1 = (const float*)d_in[2];
    const float* t1 = (const float*)d_in[3];
    const float* p2 = (const float*)d_in[4];
    const float* t2 = (const float*)d_in[5];
    const float* bboxes = (const float*)d_in[6];
    const int* bidx = (const int*)d_in[8];
    const int nbox = in_sizes[8];
    float* out = (float*)d_out;

    zero_kernel<<<100, 256>>>();
    scatter_kernel<<<3 * nbox, 256>>>(bboxes, bidx, nbox);
    reduce_kernel<<<GRID_R, 256>>>(
        (const float4*)p0, (const float4*)t0,
        (const float4*)p1, (const float4*)t1,
        (const float4*)p2, (const float4*)t2, out);
}